// round 10
// baseline (speedup 1.0000x reference)
#include <cuda_runtime.h>
#include <cstdint>

#define DD 128
#define NMAX 50000
#define EMAX 800000
#define LAYERS 3
#define EPSV 1e-5f
#define PADK 136   // padded row stride: bank = (8*k + idx) mod 32 -> conflict-free frags

// ---- scratch (no allocs allowed) ----
__device__ float g_m[NMAX * DD];     // m = h @ W
__device__ float g_agg[NMAX * DD];   // aggregated messages (pre-BN)
__device__ float g_dinv[NMAX];       // rsqrt(deg)
__device__ int   g_cnt[NMAX];        // in-edge count per dst (no self-loop)
__device__ int   g_off[NMAX];        // per-node segment start (unordered alloc)
__device__ int   g_cur[NMAX];        // scatter cursors
__device__ int   g_total;            // segment allocator
__device__ int   g_es[EMAX];         // dst-grouped src ids
__device__ float g_ew[EMAX];         // dst-grouped edge weights dinv[s]*dinv[t]
__device__ uint32_t g_whi[LAYERS * DD * DD];  // W split hi (tf32 bits)
__device__ uint32_t g_wlo[LAYERS * DD * DD];  // W split lo (tf32 bits)
__device__ float g_sum[DD];
__device__ float g_sumsq[DD];
__device__ float g_scale[DD];
__device__ float g_shift[DD];

// ---------------- CSR construction (proven) ----------------
__global__ void zero_cnt_kernel(int n) {
    int i = blockIdx.x * blockDim.x + threadIdx.x;
    if (i < n) g_cnt[i] = 0;
    if (i == 0) g_total = 0;
}

__global__ void hist_kernel(const int* __restrict__ dst, int E) {
    int e = blockIdx.x * blockDim.x + threadIdx.x;
    if (e < E) atomicAdd(&g_cnt[dst[e]], 1);
}

__global__ void dinv_kernel(int n) {
    int i = blockIdx.x * blockDim.x + threadIdx.x;
    if (i < n) g_dinv[i] = rsqrtf((float)(g_cnt[i] + 1));  // +1 self-loop
}

__global__ void alloc_off_kernel(int n) {
    int i = blockIdx.x * blockDim.x + threadIdx.x;
    if (i >= n) return;
    int c = g_cnt[i];
    int pos = (c > 0) ? atomicAdd(&g_total, c) : 0;
    g_off[i] = pos;
    g_cur[i] = pos;
}

__global__ void edge_sort_kernel(const int* __restrict__ src,
                                 const int* __restrict__ dst, int E) {
    int e = blockIdx.x * blockDim.x + threadIdx.x;
    if (e >= E) return;
    int s = src[e], t = dst[e];
    int pos = atomicAdd(&g_cur[t], 1);
    g_es[pos] = s;
    g_ew[pos] = g_dinv[s] * g_dinv[t];
}

// ---------------- tf32 helpers ----------------
__device__ __forceinline__ void split_tf32(float v, uint32_t& hi, uint32_t& lo) {
    uint32_t h;
    asm("cvt.rna.tf32.f32 %0, %1;" : "=r"(h) : "f"(v));
    float l = v - __uint_as_float(h);
    uint32_t lw;
    asm("cvt.rna.tf32.f32 %0, %1;" : "=r"(lw) : "f"(l));
    hi = h; lo = lw;
}

__device__ __forceinline__ void mma_tf32(float* c, uint32_t a0, uint32_t a1,
                                         uint32_t a2, uint32_t a3,
                                         uint32_t b0, uint32_t b1) {
    asm volatile(
        "mma.sync.aligned.m16n8k8.row.col.f32.tf32.tf32.f32 "
        "{%0,%1,%2,%3}, {%4,%5,%6,%7}, {%8,%9}, {%0,%1,%2,%3};"
        : "+f"(c[0]), "+f"(c[1]), "+f"(c[2]), "+f"(c[3])
        : "r"(a0), "r"(a1), "r"(a2), "r"(a3), "r"(b0), "r"(b1));
}

// ---------------- W pre-split (once per launch) ----------------
__global__ void split_w_kernel(const float* __restrict__ W, int total) {
    int i = blockIdx.x * blockDim.x + threadIdx.x;
    if (i >= total) return;
    uint32_t h, l;
    split_tf32(W[i], h, l);
    g_whi[i] = h;
    g_wlo[i] = l;
}

// ---------------- GEMM (tensor core, 3xTF32, pre-split W): m = act(h) @ W ----
// 128 rows x 128 cols per block, 256 threads (8 warps, 4x2 warp grid).
// Warp tile: 32 rows x 64 cols = 2 m-tiles x 8 n-tiles of m16n8k8. K-chunk 16.
__global__ __launch_bounds__(256) void gemm_tc_kernel(
    const float* __restrict__ x, int fused, int loff, int n)
{
    const float* __restrict__ in = fused ? g_agg : x;
    __shared__ float    aT[16][PADK];   // [k][row] transposed A chunk
    __shared__ uint32_t bsh[16][PADK];  // [k][col] W hi chunk
    __shared__ uint32_t bsl[16][PADK];  // [k][col] W lo chunk
    __shared__ float s_scale[DD], s_shift[DD];

    int tid = threadIdx.x;
    if (tid < DD) {
        s_scale[tid] = fused ? g_scale[tid] : 1.0f;
        s_shift[tid] = fused ? g_shift[tid] : 0.0f;
    }
    __syncthreads();

    int lane = tid & 31;
    int warp = tid >> 5;
    int warp_m = warp >> 1;            // 0..3  -> rows warp_m*32 .. +31
    int warp_n = warp & 1;             // 0..1  -> cols warp_n*64 .. +63
    int row0 = blockIdx.x * 128;

    float acc[2][8][4];
#pragma unroll
    for (int mt = 0; mt < 2; mt++)
#pragma unroll
        for (int nt = 0; nt < 8; nt++)
#pragma unroll
            for (int i = 0; i < 4; i++) acc[mt][nt][i] = 0.0f;

    int lq = lane >> 2;   // 0..7
    int lr = lane & 3;    // 0..3

    for (int kt = 0; kt < DD; kt += 16) {
        // A chunk: 128 rows x 16 k, stored transposed. 512 float4 gmem loads.
        for (int q = tid; q < 512; q += 256) {
            int kq = q >> 7, row = q & 127;     // lanes -> consecutive rows
            int gr = row0 + row;
            float4 v = make_float4(0.f, 0.f, 0.f, 0.f);
            if (gr < n)
                v = *(const float4*)(in + (size_t)gr * DD + kt + kq * 4);
            if (fused) {
                int k = kt + kq * 4;
                v.x = fmaxf(0.f, v.x * s_scale[k + 0] + s_shift[k + 0]);
                v.y = fmaxf(0.f, v.y * s_scale[k + 1] + s_shift[k + 1]);
                v.z = fmaxf(0.f, v.z * s_scale[k + 2] + s_shift[k + 2]);
                v.w = fmaxf(0.f, v.w * s_scale[k + 3] + s_shift[k + 3]);
            }
            aT[kq * 4 + 0][row] = v.x;
            aT[kq * 4 + 1][row] = v.y;
            aT[kq * 4 + 2][row] = v.z;
            aT[kq * 4 + 3][row] = v.w;
        }
        // W chunks: 16 k x 128 cols hi + lo, coalesced uint4 loads.
        for (int q = tid; q < 512; q += 256) {
            int r = q >> 5, cq = q & 31;
            size_t gidx = (size_t)loff + (size_t)(kt + r) * DD + cq * 4;
            *(uint4*)&bsh[r][cq * 4] = *(const uint4*)(g_whi + gidx);
            *(uint4*)&bsl[r][cq * 4] = *(const uint4*)(g_wlo + gidx);
        }
        __syncthreads();

#pragma unroll
        for (int ks = 0; ks < 2; ks++) {
            int kk = ks * 8;
            // A fragments for 2 m-tiles, split hi/lo
            uint32_t ah[2][4], al[2][4];
#pragma unroll
            for (int mt = 0; mt < 2; mt++) {
                int rb = warp_m * 32 + mt * 16 + lq;
                float f0 = aT[kk + lr][rb];
                float f1 = aT[kk + lr][rb + 8];
                float f2 = aT[kk + lr + 4][rb];
                float f3 = aT[kk + lr + 4][rb + 8];
                split_tf32(f0, ah[mt][0], al[mt][0]);
                split_tf32(f1, ah[mt][1], al[mt][1]);
                split_tf32(f2, ah[mt][2], al[mt][2]);
                split_tf32(f3, ah[mt][3], al[mt][3]);
            }
#pragma unroll
            for (int nt = 0; nt < 8; nt++) {
                int cb = warp_n * 64 + nt * 8 + lq;
                uint32_t bh0 = bsh[kk + lr][cb];
                uint32_t bh1 = bsh[kk + lr + 4][cb];
                uint32_t bl0 = bsl[kk + lr][cb];
                uint32_t bl1 = bsl[kk + lr + 4][cb];
#pragma unroll
                for (int mt = 0; mt < 2; mt++) {
                    mma_tf32(acc[mt][nt], ah[mt][0], ah[mt][1], ah[mt][2], ah[mt][3], bh0, bh1);
                    mma_tf32(acc[mt][nt], al[mt][0], al[mt][1], al[mt][2], al[mt][3], bh0, bh1);
                    mma_tf32(acc[mt][nt], ah[mt][0], ah[mt][1], ah[mt][2], ah[mt][3], bl0, bl1);
                }
            }
        }
        __syncthreads();
    }

    // epilogue: c0,c1 at (row, 2c), (row, 2c+1); c2,c3 at row+8
#pragma unroll
    for (int mt = 0; mt < 2; mt++) {
        int gr0 = row0 + warp_m * 32 + mt * 16 + lq;
#pragma unroll
        for (int nt = 0; nt < 8; nt++) {
            int gc = warp_n * 64 + nt * 8 + lr * 2;
            if (gr0 < n)
                *(float2*)(g_m + (size_t)gr0 * DD + gc) =
                    make_float2(acc[mt][nt][0], acc[mt][nt][1]);
            if (gr0 + 8 < n)
                *(float2*)(g_m + (size_t)(gr0 + 8) * DD + gc) =
                    make_float2(acc[mt][nt][2], acc[mt][nt][3]);
        }
    }
}

// ---------------- gather + fused BN stats (proven) ----------------
__global__ __launch_bounds__(256) void gather_stats_kernel(int n) {
    __shared__ float s_sum[8][DD];
    __shared__ float s_sq[8][DD];

    int tid = threadIdx.x;
    int lane = tid & 31;
    int warp = tid >> 5;
    int gwarp = blockIdx.x * 8 + warp;
    int nwarps = gridDim.x * 8;
    const float4* __restrict__ m4 = (const float4*)g_m;

    float4 lsum = make_float4(0.f, 0.f, 0.f, 0.f);
    float4 lsq  = make_float4(0.f, 0.f, 0.f, 0.f);

    for (int node = gwarp; node < n; node += nwarps) {
        float di = g_dinv[node];
        float w0 = di * di;
        float4 acc = m4[(size_t)node * 32 + lane];
        acc.x *= w0; acc.y *= w0; acc.z *= w0; acc.w *= w0;

        int beg = g_off[node];
        int cnt = g_cnt[node];
        for (int i = 0; i < cnt; i++) {
            int s = g_es[beg + i];
            float w = g_ew[beg + i];
            float4 v = m4[(size_t)s * 32 + lane];
            acc.x += w * v.x;
            acc.y += w * v.y;
            acc.z += w * v.z;
            acc.w += w * v.w;
        }
        ((float4*)g_agg)[(size_t)node * 32 + lane] = acc;

        lsum.x += acc.x; lsum.y += acc.y; lsum.z += acc.z; lsum.w += acc.w;
        lsq.x += acc.x * acc.x; lsq.y += acc.y * acc.y;
        lsq.z += acc.z * acc.z; lsq.w += acc.w * acc.w;
    }

    *(float4*)&s_sum[warp][lane * 4] = lsum;
    *(float4*)&s_sq[warp][lane * 4]  = lsq;
    __syncthreads();

    if (tid < DD) {
        float a = 0.f, b = 0.f;
#pragma unroll
        for (int w = 0; w < 8; w++) {
            a += s_sum[w][tid];
            b += s_sq[w][tid];
        }
        atomicAdd(&g_sum[tid], a);
        atomicAdd(&g_sumsq[tid], b);
    }
}

// ---------------- batchnorm finalize ----------------
__global__ void zero_stats_kernel() {
    int d = threadIdx.x;
    g_sum[d] = 0.0f;
    g_sumsq[d] = 0.0f;
}

// GCN bias b cancels inside BN (mean shifts by b, variance unchanged) -> skip it.
__global__ void finalize_stats_kernel(const float* __restrict__ gamma,
                                      const float* __restrict__ beta, float inv_n) {
    int d = threadIdx.x;
    float mu = g_sum[d] * inv_n;
    float var = g_sumsq[d] * inv_n - mu * mu;
    float rstd = rsqrtf(var + EPSV);
    float sc = gamma[d] * rstd;
    g_scale[d] = sc;
    g_shift[d] = beta[d] - mu * sc;
}

// ---------------- final normalize + relu -> out ----------------
__global__ void norm_relu_kernel(float* __restrict__ out, int n) {
    int idx = blockIdx.x * blockDim.x + threadIdx.x;  // float4 index
    int total = n * (DD / 4);
    if (idx >= total) return;
    int c4 = (idx & 31) * 4;
    float4 v = reinterpret_cast<const float4*>(g_agg)[idx];
    float4 r;
    r.x = fmaxf(0.0f, v.x * g_scale[c4 + 0] + g_shift[c4 + 0]);
    r.y = fmaxf(0.0f, v.y * g_scale[c4 + 1] + g_shift[c4 + 1]);
    r.z = fmaxf(0.0f, v.z * g_scale[c4 + 2] + g_shift[c4 + 2]);
    r.w = fmaxf(0.0f, v.w * g_scale[c4 + 3] + g_shift[c4 + 3]);
    reinterpret_cast<float4*>(out)[idx] = r;
}

// ---------------- launcher ----------------
extern "C" void kernel_launch(void* const* d_in, const int* in_sizes, int n_in,
                              void* d_out, int out_size) {
    const float* x     = (const float*)d_in[0];
    const int*   ei    = (const int*)d_in[1];
    const float* W     = (const float*)d_in[2];
    // d_in[3] = b : mathematically absorbed by batchnorm, unused
    const float* gamma = (const float*)d_in[4];
    const float* beta  = (const float*)d_in[5];
    float* out = (float*)d_out;

    int n = in_sizes[0] / DD;
    int E = in_sizes[1] / 2;
    const int* src = ei;
    const int* dst = ei + E;

    // W pre-split + CSR build (once per launch)
    split_w_kernel<<<(LAYERS * DD * DD + 255) / 256, 256>>>(W, LAYERS * DD * DD);
    zero_cnt_kernel<<<(n + 255) / 256, 256>>>(n);
    hist_kernel<<<(E + 255) / 256, 256>>>(dst, E);
    dinv_kernel<<<(n + 255) / 256, 256>>>(n);
    alloc_off_kernel<<<(n + 255) / 256, 256>>>(n);
    edge_sort_kernel<<<(E + 255) / 256, 256>>>(src, dst, E);

    int elem4 = n * (DD / 4);
    for (int l = 0; l < LAYERS; l++) {
        gemm_tc_kernel<<<(n + 127) / 128, 256>>>(x, (l == 0) ? 0 : 1,
                                                 l * DD * DD, n);
        zero_stats_kernel<<<1, DD>>>();
        gather_stats_kernel<<<512, 256>>>(n);
        finalize_stats_kernel<<<1, DD>>>(gamma + (size_t)l * DD,
                                         beta + (size_t)l * DD, 1.0f / (float)n);
    }
    norm_relu_kernel<<<(elem4 + 255) / 256, 256>>>(out, n);
}

// round 13
// speedup vs baseline: 1.1072x; 1.1072x over previous
#include <cuda_runtime.h>
#include <cstdint>

#define DD 128
#define NMAX 50000
#define EMAX 800000
#define LAYERS 3
#define EPSV 1e-5f
#define PADK 136   // stride mod 32 = 8 -> bank = 8*lr + lq + c : conflict-free frags

// dynamic smem for gemm: aT(32*PADK f32) + bsh(32*PADK u32) + bsl + scale + shift
#define SMEM_GEMM (32 * PADK * 4 * 3 + 2 * DD * 4)

// ---- scratch (no allocs allowed) ----
__device__ float g_m[NMAX * DD];     // m = h @ W
__device__ float g_agg[NMAX * DD];   // aggregated messages (pre-BN)
__device__ float g_dinv[NMAX];       // rsqrt(deg)
__device__ int   g_cnt[NMAX];        // in-edge count per dst (no self-loop)
__device__ int   g_off[NMAX];        // per-node segment start (unordered alloc)
__device__ int   g_cur[NMAX];        // scatter cursors
__device__ int   g_total;            // segment allocator
__device__ int   g_es[EMAX];         // dst-grouped src ids
__device__ float g_ew[EMAX];         // dst-grouped edge weights dinv[s]*dinv[t]
__device__ uint32_t g_whi[LAYERS * DD * DD];  // W split hi (tf32 bits)
__device__ uint32_t g_wlo[LAYERS * DD * DD];  // W split lo (tf32 bits)
__device__ float g_sumL[LAYERS * DD];         // per-layer BN sums
__device__ float g_sumsqL[LAYERS * DD];

// ---------------- tf32 helpers ----------------
__device__ __forceinline__ void split_tf32(float v, uint32_t& hi, uint32_t& lo) {
    uint32_t h;
    asm("cvt.rna.tf32.f32 %0, %1;" : "=r"(h) : "f"(v));
    float l = v - __uint_as_float(h);
    uint32_t lw;
    asm("cvt.rna.tf32.f32 %0, %1;" : "=r"(lw) : "f"(l));
    hi = h; lo = lw;
}

__device__ __forceinline__ void mma_tf32(float* c, uint32_t a0, uint32_t a1,
                                         uint32_t a2, uint32_t a3,
                                         uint32_t b0, uint32_t b1) {
    asm volatile(
        "mma.sync.aligned.m16n8k8.row.col.f32.tf32.tf32.f32 "
        "{%0,%1,%2,%3}, {%4,%5,%6,%7}, {%8,%9}, {%0,%1,%2,%3};"
        : "+f"(c[0]), "+f"(c[1]), "+f"(c[2]), "+f"(c[3])
        : "r"(a0), "r"(a1), "r"(a2), "r"(a3), "r"(b0), "r"(b1));
}

// ---------------- setup: split W + zero cnt/stats (one launch) ----------------
__global__ void setup_kernel(const float* __restrict__ W, int n) {
    int i = blockIdx.x * blockDim.x + threadIdx.x;
    if (i < LAYERS * DD * DD) {
        uint32_t h, l;
        split_tf32(W[i], h, l);
        g_whi[i] = h;
        g_wlo[i] = l;
    }
    if (i < n) g_cnt[i] = 0;
    if (i < LAYERS * DD) { g_sumL[i] = 0.f; g_sumsqL[i] = 0.f; }
    if (i == 0) g_total = 0;
}

// ---------------- CSR construction ----------------
__global__ void hist_kernel(const int* __restrict__ dst, int E) {
    int e = blockIdx.x * blockDim.x + threadIdx.x;
    if (e < E) atomicAdd(&g_cnt[dst[e]], 1);
}

// dinv + unordered segment allocation, fused
__global__ void alloc_dinv_kernel(int n) {
    int i = blockIdx.x * blockDim.x + threadIdx.x;
    if (i >= n) return;
    int c = g_cnt[i];
    g_dinv[i] = rsqrtf((float)(c + 1));  // +1 self-loop
    int pos = (c > 0) ? atomicAdd(&g_total, c) : 0;
    g_off[i] = pos;
    g_cur[i] = pos;
}

__global__ void edge_sort_kernel(const int* __restrict__ src,
                                 const int* __restrict__ dst, int E) {
    int e = blockIdx.x * blockDim.x + threadIdx.x;
    if (e >= E) return;
    int s = src[e], t = dst[e];
    int pos = atomicAdd(&g_cur[t], 1);
    g_es[pos] = s;
    g_ew[pos] = g_dinv[s] * g_dinv[t];
}

// ---------------- GEMM (3xTF32, pre-split W, K-chunk 32): m = act(h) @ W ----
// 128 rows x 128 cols per block, 256 threads (8 warps, 4x2 warp grid).
// fused=1: BN scale/shift computed in prologue from raw sums; input gets BN+ReLU.
__global__ __launch_bounds__(256) void gemm_tc_kernel(
    const float* __restrict__ x, int fused, int l,
    const float* __restrict__ gamma, const float* __restrict__ beta,
    float inv_n, int n)
{
    extern __shared__ char dyn[];
    float*    aT  = (float*)dyn;                          // [32][PADK]
    uint32_t* bsh = (uint32_t*)(dyn + 32 * PADK * 4);     // [32][PADK]
    uint32_t* bsl = bsh + 32 * PADK;                      // [32][PADK]
    float* s_scale = (float*)(bsl + 32 * PADK);
    float* s_shift = s_scale + DD;

    const float* __restrict__ in = fused ? g_agg : x;
    int tid = threadIdx.x;
    if (tid < DD) {
        if (fused) {
            int pl = l - 1;
            float mu = g_sumL[pl * DD + tid] * inv_n;
            float var = g_sumsqL[pl * DD + tid] * inv_n - mu * mu;
            float rstd = rsqrtf(var + EPSV);
            float sc = gamma[pl * DD + tid] * rstd;
            s_scale[tid] = sc;
            s_shift[tid] = beta[pl * DD + tid] - mu * sc;
        } else {
            s_scale[tid] = 1.0f;
            s_shift[tid] = 0.0f;
        }
    }
    __syncthreads();

    int lane = tid & 31;
    int warp = tid >> 5;
    int warp_m = warp >> 1;            // rows warp_m*32 .. +31
    int warp_n = warp & 1;             // cols warp_n*64 .. +63
    int row0 = blockIdx.x * 128;
    int loff = l * DD * DD;

    float acc[2][8][4];
#pragma unroll
    for (int mt = 0; mt < 2; mt++)
#pragma unroll
        for (int nt = 0; nt < 8; nt++)
#pragma unroll
            for (int i = 0; i < 4; i++) acc[mt][nt][i] = 0.0f;

    int lq = lane >> 2;   // 0..7
    int lr = lane & 3;    // 0..3

    for (int kt = 0; kt < DD; kt += 32) {
        // A chunk: 128 rows x 32 k, stored transposed. 1024 float4 gmem loads.
        for (int q = tid; q < 1024; q += 256) {
            int kq = q >> 7, row = q & 127;
            int gr = row0 + row;
            float4 v = make_float4(0.f, 0.f, 0.f, 0.f);
            if (gr < n)
                v = *(const float4*)(in + (size_t)gr * DD + kt + kq * 4);
            if (fused) {
                int k = kt + kq * 4;
                v.x = fmaxf(0.f, v.x * s_scale[k + 0] + s_shift[k + 0]);
                v.y = fmaxf(0.f, v.y * s_scale[k + 1] + s_shift[k + 1]);
                v.z = fmaxf(0.f, v.z * s_scale[k + 2] + s_shift[k + 2]);
                v.w = fmaxf(0.f, v.w * s_scale[k + 3] + s_shift[k + 3]);
            }
            aT[(kq * 4 + 0) * PADK + row] = v.x;
            aT[(kq * 4 + 1) * PADK + row] = v.y;
            aT[(kq * 4 + 2) * PADK + row] = v.z;
            aT[(kq * 4 + 3) * PADK + row] = v.w;
        }
        // W chunks hi+lo: 32 k x 128 cols each, coalesced uint4 loads.
        for (int q = tid; q < 1024; q += 256) {
            int r = q >> 5, cq = q & 31;
            size_t gidx = (size_t)loff + (size_t)(kt + r) * DD + cq * 4;
            *(uint4*)&bsh[r * PADK + cq * 4] = *(const uint4*)(g_whi + gidx);
            *(uint4*)&bsl[r * PADK + cq * 4] = *(const uint4*)(g_wlo + gidx);
        }
        __syncthreads();

#pragma unroll
        for (int ks = 0; ks < 4; ks++) {
            int kk = ks * 8;
            uint32_t ah[2][4], al[2][4];
#pragma unroll
            for (int mt = 0; mt < 2; mt++) {
                int rb = warp_m * 32 + mt * 16 + lq;
                float f0 = aT[(kk + lr) * PADK + rb];
                float f1 = aT[(kk + lr) * PADK + rb + 8];
                float f2 = aT[(kk + lr + 4) * PADK + rb];
                float f3 = aT[(kk + lr + 4) * PADK + rb + 8];
                split_tf32(f0, ah[mt][0], al[mt][0]);
                split_tf32(f1, ah[mt][1], al[mt][1]);
                split_tf32(f2, ah[mt][2], al[mt][2]);
                split_tf32(f3, ah[mt][3], al[mt][3]);
            }
#pragma unroll
            for (int nt = 0; nt < 8; nt++) {
                int cb = warp_n * 64 + nt * 8 + lq;
                uint32_t bh0 = bsh[(kk + lr) * PADK + cb];
                uint32_t bh1 = bsh[(kk + lr + 4) * PADK + cb];
                uint32_t bl0 = bsl[(kk + lr) * PADK + cb];
                uint32_t bl1 = bsl[(kk + lr + 4) * PADK + cb];
#pragma unroll
                for (int mt = 0; mt < 2; mt++) {
                    mma_tf32(acc[mt][nt], ah[mt][0], ah[mt][1], ah[mt][2], ah[mt][3], bh0, bh1);
                    mma_tf32(acc[mt][nt], al[mt][0], al[mt][1], al[mt][2], al[mt][3], bh0, bh1);
                    mma_tf32(acc[mt][nt], ah[mt][0], ah[mt][1], ah[mt][2], ah[mt][3], bl0, bl1);
                }
            }
        }
        __syncthreads();
    }

    // epilogue
#pragma unroll
    for (int mt = 0; mt < 2; mt++) {
        int gr0 = row0 + warp_m * 32 + mt * 16 + lq;
#pragma unroll
        for (int nt = 0; nt < 8; nt++) {
            int gc = warp_n * 64 + nt * 8 + lr * 2;
            if (gr0 < n)
                *(float2*)(g_m + (size_t)gr0 * DD + gc) =
                    make_float2(acc[mt][nt][0], acc[mt][nt][1]);
            if (gr0 + 8 < n)
                *(float2*)(g_m + (size_t)(gr0 + 8) * DD + gc) =
                    make_float2(acc[mt][nt][2], acc[mt][nt][3]);
        }
    }
}

// ---------------- gather + fused BN stats (proven; per-layer stat buffers) ----
__global__ __launch_bounds__(256) void gather_stats_kernel(int l, int n) {
    __shared__ float s_sum[8][DD];
    __shared__ float s_sq[8][DD];

    int tid = threadIdx.x;
    int lane = tid & 31;
    int warp = tid >> 5;
    int gwarp = blockIdx.x * 8 + warp;
    int nwarps = gridDim.x * 8;
    const float4* __restrict__ m4 = (const float4*)g_m;

    float4 lsum = make_float4(0.f, 0.f, 0.f, 0.f);
    float4 lsq  = make_float4(0.f, 0.f, 0.f, 0.f);

    for (int node = gwarp; node < n; node += nwarps) {
        float di = g_dinv[node];
        float w0 = di * di;
        float4 acc = m4[(size_t)node * 32 + lane];
        acc.x *= w0; acc.y *= w0; acc.z *= w0; acc.w *= w0;

        int beg = g_off[node];
        int cnt = g_cnt[node];
        for (int i = 0; i < cnt; i++) {
            int s = g_es[beg + i];
            float w = g_ew[beg + i];
            float4 v = m4[(size_t)s * 32 + lane];
            acc.x += w * v.x;
            acc.y += w * v.y;
            acc.z += w * v.z;
            acc.w += w * v.w;
        }
        ((float4*)g_agg)[(size_t)node * 32 + lane] = acc;

        lsum.x += acc.x; lsum.y += acc.y; lsum.z += acc.z; lsum.w += acc.w;
        lsq.x += acc.x * acc.x; lsq.y += acc.y * acc.y;
        lsq.z += acc.z * acc.z; lsq.w += acc.w * acc.w;
    }

    *(float4*)&s_sum[warp][lane * 4] = lsum;
    *(float4*)&s_sq[warp][lane * 4]  = lsq;
    __syncthreads();

    if (tid < DD) {
        float a = 0.f, b = 0.f;
#pragma unroll
        for (int w = 0; w < 8; w++) {
            a += s_sum[w][tid];
            b += s_sq[w][tid];
        }
        atomicAdd(&g_sumL[l * DD + tid], a);
        atomicAdd(&g_sumsqL[l * DD + tid], b);
    }
}

// ---------------- final normalize + relu -> out (computes own scale/shift) ----
__global__ void norm_relu_kernel(float* __restrict__ out,
                                 const float* __restrict__ gamma,
                                 const float* __restrict__ beta,
                                 float inv_n, int n) {
    __shared__ float s_scale[DD], s_shift[DD];
    int tid = threadIdx.x;
    if (tid < DD) {
        int pl = LAYERS - 1;
        float mu = g_sumL[pl * DD + tid] * inv_n;
        float var = g_sumsqL[pl * DD + tid] * inv_n - mu * mu;
        float rstd = rsqrtf(var + EPSV);
        float sc = gamma[pl * DD + tid] * rstd;
        s_scale[tid] = sc;
        s_shift[tid] = beta[pl * DD + tid] - mu * sc;
    }
    __syncthreads();

    int total = n * (DD / 4);
    for (int idx = blockIdx.x * blockDim.x + tid; idx < total;
         idx += gridDim.x * blockDim.x) {
        int c4 = (idx & 31) * 4;
        float4 v = ((const float4*)g_agg)[idx];
        float4 r;
        r.x = fmaxf(0.0f, v.x * s_scale[c4 + 0] + s_shift[c4 + 0]);
        r.y = fmaxf(0.0f, v.y * s_scale[c4 + 1] + s_shift[c4 + 1]);
        r.z = fmaxf(0.0f, v.z * s_scale[c4 + 2] + s_shift[c4 + 2]);
        r.w = fmaxf(0.0f, v.w * s_scale[c4 + 3] + s_shift[c4 + 3]);
        ((float4*)out)[idx] = r;
    }
}

// ---------------- launcher ----------------
extern "C" void kernel_launch(void* const* d_in, const int* in_sizes, int n_in,
                              void* d_out, int out_size) {
    const float* x     = (const float*)d_in[0];
    const int*   ei    = (const int*)d_in[1];
    const float* W     = (const float*)d_in[2];
    // d_in[3] = b : mathematically absorbed by batchnorm, unused
    const float* gamma = (const float*)d_in[4];
    const float* beta  = (const float*)d_in[5];
    float* out = (float*)d_out;

    int n = in_sizes[0] / DD;
    int E = in_sizes[1] / 2;
    const int* src = ei;
    const int* dst = ei + E;
    float inv_n = 1.0f / (float)n;

    cudaFuncSetAttribute(gemm_tc_kernel,
                         cudaFuncAttributeMaxDynamicSharedMemorySize, SMEM_GEMM);

    int setup_elems = (LAYERS * DD * DD > n) ? LAYERS * DD * DD : n;
    setup_kernel<<<(setup_elems + 255) / 256, 256>>>(W, n);
    hist_kernel<<<(E + 255) / 256, 256>>>(dst, E);
    alloc_dinv_kernel<<<(n + 255) / 256, 256>>>(n);
    edge_sort_kernel<<<(E + 255) / 256, 256>>>(src, dst, E);

    for (int l = 0; l < LAYERS; l++) {
        gemm_tc_kernel<<<(n + 127) / 128, 256, SMEM_GEMM>>>(
            x, (l == 0) ? 0 : 1, l, gamma, beta, inv_n, n);
        gather_stats_kernel<<<512, 256>>>(l, n);
    }
    norm_relu_kernel<<<512, 256>>>(out, gamma, beta, inv_n, n);
}

// round 14
// speedup vs baseline: 1.1246x; 1.0158x over previous
#include <cuda_runtime.h>
#include <cstdint>

#define DD 128
#define NMAX 50000
#define EMAX 800000
#define LAYERS 3
#define EPSV 1e-5f
#define PADK 136   // stride mod 32 = 8 -> bank = 8*lr + lq + c : conflict-free frags

// dynamic smem for gemm: aT(32*PADK f32) + bsh(32*PADK u32) + bsl + scale + shift
#define SMEM_GEMM (32 * PADK * 4 * 3 + 2 * DD * 4)

// ---- scratch (no allocs allowed) ----
__device__ float g_m[NMAX * DD];     // m = h @ W
__device__ float g_agg[NMAX * DD];   // aggregated messages (pre-BN)
__device__ float g_dinv[NMAX];       // rsqrt(deg)
__device__ int   g_cnt[NMAX];        // in-edge count per dst (no self-loop)
__device__ int   g_off[NMAX];        // per-node segment start (unordered alloc)
__device__ int   g_cur[NMAX];        // scatter cursors
__device__ int   g_total;            // segment allocator
__device__ int   g_es[EMAX];         // dst-grouped src ids
__device__ float g_ew[EMAX];         // dst-grouped edge weights dinv[s]*dinv[t]
__device__ uint32_t g_whi[LAYERS * DD * DD];  // W split hi (tf32 bits)
__device__ uint32_t g_wlo[LAYERS * DD * DD];  // W split lo (tf32 bits)
__device__ float g_sumL[LAYERS * DD];         // per-layer BN sums
__device__ float g_sumsqL[LAYERS * DD];

// ---------------- tf32 helpers ----------------
__device__ __forceinline__ void split_tf32(float v, uint32_t& hi, uint32_t& lo) {
    uint32_t h;
    asm("cvt.rna.tf32.f32 %0, %1;" : "=r"(h) : "f"(v));
    float l = v - __uint_as_float(h);
    uint32_t lw;
    asm("cvt.rna.tf32.f32 %0, %1;" : "=r"(lw) : "f"(l));
    hi = h; lo = lw;
}

__device__ __forceinline__ void mma_tf32(float* c, uint32_t a0, uint32_t a1,
                                         uint32_t a2, uint32_t a3,
                                         uint32_t b0, uint32_t b1) {
    asm volatile(
        "mma.sync.aligned.m16n8k8.row.col.f32.tf32.tf32.f32 "
        "{%0,%1,%2,%3}, {%4,%5,%6,%7}, {%8,%9}, {%0,%1,%2,%3};"
        : "+f"(c[0]), "+f"(c[1]), "+f"(c[2]), "+f"(c[3])
        : "r"(a0), "r"(a1), "r"(a2), "r"(a3), "r"(b0), "r"(b1));
}

// ---------------- GEMM-chain setup: split W + zero stats ----------------
__global__ void split_w_kernel(const float* __restrict__ W) {
    int i = blockIdx.x * blockDim.x + threadIdx.x;
    if (i < LAYERS * DD * DD) {
        uint32_t h, l;
        split_tf32(W[i], h, l);
        g_whi[i] = h;
        g_wlo[i] = l;
    }
    if (i < LAYERS * DD) { g_sumL[i] = 0.f; g_sumsqL[i] = 0.f; }
}

// ---------------- CSR chain ----------------
__global__ void zero_cnt_kernel(int n) {
    int i = blockIdx.x * blockDim.x + threadIdx.x;
    if (i < n) g_cnt[i] = 0;
    if (i == 0) g_total = 0;
}

__global__ void hist_kernel(const int* __restrict__ dst, int E) {
    int e = blockIdx.x * blockDim.x + threadIdx.x;
    if (e < E) atomicAdd(&g_cnt[dst[e]], 1);
}

// dinv + unordered segment allocation, fused
__global__ void alloc_dinv_kernel(int n) {
    int i = blockIdx.x * blockDim.x + threadIdx.x;
    if (i >= n) return;
    int c = g_cnt[i];
    g_dinv[i] = rsqrtf((float)(c + 1));  // +1 self-loop
    int pos = (c > 0) ? atomicAdd(&g_total, c) : 0;
    g_off[i] = pos;
    g_cur[i] = pos;
}

__global__ void edge_sort_kernel(const int* __restrict__ src,
                                 const int* __restrict__ dst, int E) {
    int e = blockIdx.x * blockDim.x + threadIdx.x;
    if (e >= E) return;
    int s = src[e], t = dst[e];
    int pos = atomicAdd(&g_cur[t], 1);
    g_es[pos] = s;
    g_ew[pos] = g_dinv[s] * g_dinv[t];
}

// ---------------- GEMM (3xTF32, pre-split W, K-chunk 32): m = act(h) @ W ----
// 128 rows x 128 cols per block, 256 threads (8 warps, 4x2 warp grid).
// fused=1: BN scale/shift computed in prologue from raw sums; input gets BN+ReLU.
__global__ __launch_bounds__(256) void gemm_tc_kernel(
    const float* __restrict__ x, int fused, int l,
    const float* __restrict__ gamma, const float* __restrict__ beta,
    float inv_n, int n)
{
    extern __shared__ char dyn[];
    float*    aT  = (float*)dyn;                          // [32][PADK]
    uint32_t* bsh = (uint32_t*)(dyn + 32 * PADK * 4);     // [32][PADK]
    uint32_t* bsl = bsh + 32 * PADK;                      // [32][PADK]
    float* s_scale = (float*)(bsl + 32 * PADK);
    float* s_shift = s_scale + DD;

    const float* __restrict__ in = fused ? g_agg : x;
    int tid = threadIdx.x;
    if (tid < DD) {
        if (fused) {
            int pl = l - 1;
            float mu = g_sumL[pl * DD + tid] * inv_n;
            float var = g_sumsqL[pl * DD + tid] * inv_n - mu * mu;
            float rstd = rsqrtf(var + EPSV);
            float sc = gamma[pl * DD + tid] * rstd;
            s_scale[tid] = sc;
            s_shift[tid] = beta[pl * DD + tid] - mu * sc;
        } else {
            s_scale[tid] = 1.0f;
            s_shift[tid] = 0.0f;
        }
    }
    __syncthreads();

    int lane = tid & 31;
    int warp = tid >> 5;
    int warp_m = warp >> 1;            // rows warp_m*32 .. +31
    int warp_n = warp & 1;             // cols warp_n*64 .. +63
    int row0 = blockIdx.x * 128;
    int loff = l * DD * DD;

    float acc[2][8][4];
#pragma unroll
    for (int mt = 0; mt < 2; mt++)
#pragma unroll
        for (int nt = 0; nt < 8; nt++)
#pragma unroll
            for (int i = 0; i < 4; i++) acc[mt][nt][i] = 0.0f;

    int lq = lane >> 2;   // 0..7
    int lr = lane & 3;    // 0..3

    for (int kt = 0; kt < DD; kt += 32) {
        // A chunk: 128 rows x 32 k, stored transposed. 1024 float4 gmem loads.
        for (int q = tid; q < 1024; q += 256) {
            int kq = q >> 7, row = q & 127;
            int gr = row0 + row;
            float4 v = make_float4(0.f, 0.f, 0.f, 0.f);
            if (gr < n)
                v = *(const float4*)(in + (size_t)gr * DD + kt + kq * 4);
            if (fused) {
                int k = kt + kq * 4;
                v.x = fmaxf(0.f, v.x * s_scale[k + 0] + s_shift[k + 0]);
                v.y = fmaxf(0.f, v.y * s_scale[k + 1] + s_shift[k + 1]);
                v.z = fmaxf(0.f, v.z * s_scale[k + 2] + s_shift[k + 2]);
                v.w = fmaxf(0.f, v.w * s_scale[k + 3] + s_shift[k + 3]);
            }
            aT[(kq * 4 + 0) * PADK + row] = v.x;
            aT[(kq * 4 + 1) * PADK + row] = v.y;
            aT[(kq * 4 + 2) * PADK + row] = v.z;
            aT[(kq * 4 + 3) * PADK + row] = v.w;
        }
        // W chunks hi+lo: 32 k x 128 cols each, coalesced uint4 loads.
        for (int q = tid; q < 1024; q += 256) {
            int r = q >> 5, cq = q & 31;
            size_t gidx = (size_t)loff + (size_t)(kt + r) * DD + cq * 4;
            *(uint4*)&bsh[r * PADK + cq * 4] = *(const uint4*)(g_whi + gidx);
            *(uint4*)&bsl[r * PADK + cq * 4] = *(const uint4*)(g_wlo + gidx);
        }
        __syncthreads();

#pragma unroll
        for (int ks = 0; ks < 4; ks++) {
            int kk = ks * 8;
            uint32_t ah[2][4], al[2][4];
#pragma unroll
            for (int mt = 0; mt < 2; mt++) {
                int rb = warp_m * 32 + mt * 16 + lq;
                float f0 = aT[(kk + lr) * PADK + rb];
                float f1 = aT[(kk + lr) * PADK + rb + 8];
                float f2 = aT[(kk + lr + 4) * PADK + rb];
                float f3 = aT[(kk + lr + 4) * PADK + rb + 8];
                split_tf32(f0, ah[mt][0], al[mt][0]);
                split_tf32(f1, ah[mt][1], al[mt][1]);
                split_tf32(f2, ah[mt][2], al[mt][2]);
                split_tf32(f3, ah[mt][3], al[mt][3]);
            }
#pragma unroll
            for (int nt = 0; nt < 8; nt++) {
                int cb = warp_n * 64 + nt * 8 + lq;
                uint32_t bh0 = bsh[(kk + lr) * PADK + cb];
                uint32_t bh1 = bsh[(kk + lr + 4) * PADK + cb];
                uint32_t bl0 = bsl[(kk + lr) * PADK + cb];
                uint32_t bl1 = bsl[(kk + lr + 4) * PADK + cb];
#pragma unroll
                for (int mt = 0; mt < 2; mt++) {
                    mma_tf32(acc[mt][nt], ah[mt][0], ah[mt][1], ah[mt][2], ah[mt][3], bh0, bh1);
                    mma_tf32(acc[mt][nt], al[mt][0], al[mt][1], al[mt][2], al[mt][3], bh0, bh1);
                    mma_tf32(acc[mt][nt], ah[mt][0], ah[mt][1], ah[mt][2], ah[mt][3], bl0, bl1);
                }
            }
        }
        __syncthreads();
    }

    // epilogue
#pragma unroll
    for (int mt = 0; mt < 2; mt++) {
        int gr0 = row0 + warp_m * 32 + mt * 16 + lq;
#pragma unroll
        for (int nt = 0; nt < 8; nt++) {
            int gc = warp_n * 64 + nt * 8 + lr * 2;
            if (gr0 < n)
                *(float2*)(g_m + (size_t)gr0 * DD + gc) =
                    make_float2(acc[mt][nt][0], acc[mt][nt][1]);
            if (gr0 + 8 < n)
                *(float2*)(g_m + (size_t)(gr0 + 8) * DD + gc) =
                    make_float2(acc[mt][nt][2], acc[mt][nt][3]);
        }
    }
}

// ---------------- gather + fused BN stats (proven; per-layer stat buffers) ----
__global__ __launch_bounds__(256) void gather_stats_kernel(int l, int n) {
    __shared__ float s_sum[8][DD];
    __shared__ float s_sq[8][DD];

    int tid = threadIdx.x;
    int lane = tid & 31;
    int warp = tid >> 5;
    int gwarp = blockIdx.x * 8 + warp;
    int nwarps = gridDim.x * 8;
    const float4* __restrict__ m4 = (const float4*)g_m;

    float4 lsum = make_float4(0.f, 0.f, 0.f, 0.f);
    float4 lsq  = make_float4(0.f, 0.f, 0.f, 0.f);

    for (int node = gwarp; node < n; node += nwarps) {
        float di = g_dinv[node];
        float w0 = di * di;
        float4 acc = m4[(size_t)node * 32 + lane];
        acc.x *= w0; acc.y *= w0; acc.z *= w0; acc.w *= w0;

        int beg = g_off[node];
        int cnt = g_cnt[node];
        for (int i = 0; i < cnt; i++) {
            int s = g_es[beg + i];
            float w = g_ew[beg + i];
            float4 v = m4[(size_t)s * 32 + lane];
            acc.x += w * v.x;
            acc.y += w * v.y;
            acc.z += w * v.z;
            acc.w += w * v.w;
        }
        ((float4*)g_agg)[(size_t)node * 32 + lane] = acc;

        lsum.x += acc.x; lsum.y += acc.y; lsum.z += acc.z; lsum.w += acc.w;
        lsq.x += acc.x * acc.x; lsq.y += acc.y * acc.y;
        lsq.z += acc.z * acc.z; lsq.w += acc.w * acc.w;
    }

    *(float4*)&s_sum[warp][lane * 4] = lsum;
    *(float4*)&s_sq[warp][lane * 4]  = lsq;
    __syncthreads();

    if (tid < DD) {
        float a = 0.f, b = 0.f;
#pragma unroll
        for (int w = 0; w < 8; w++) {
            a += s_sum[w][tid];
            b += s_sq[w][tid];
        }
        atomicAdd(&g_sumL[l * DD + tid], a);
        atomicAdd(&g_sumsqL[l * DD + tid], b);
    }
}

// ---------------- final normalize + relu -> out (computes own scale/shift) ----
__global__ void norm_relu_kernel(float* __restrict__ out,
                                 const float* __restrict__ gamma,
                                 const float* __restrict__ beta,
                                 float inv_n, int n) {
    __shared__ float s_scale[DD], s_shift[DD];
    int tid = threadIdx.x;
    if (tid < DD) {
        int pl = LAYERS - 1;
        float mu = g_sumL[pl * DD + tid] * inv_n;
        float var = g_sumsqL[pl * DD + tid] * inv_n - mu * mu;
        float rstd = rsqrtf(var + EPSV);
        float sc = gamma[pl * DD + tid] * rstd;
        s_scale[tid] = sc;
        s_shift[tid] = beta[pl * DD + tid] - mu * sc;
    }
    __syncthreads();

    int total = n * (DD / 4);
    for (int idx = blockIdx.x * blockDim.x + tid; idx < total;
         idx += gridDim.x * blockDim.x) {
        int c4 = (idx & 31) * 4;
        float4 v = ((const float4*)g_agg)[idx];
        float4 r;
        r.x = fmaxf(0.0f, v.x * s_scale[c4 + 0] + s_shift[c4 + 0]);
        r.y = fmaxf(0.0f, v.y * s_scale[c4 + 1] + s_shift[c4 + 1]);
        r.z = fmaxf(0.0f, v.z * s_scale[c4 + 2] + s_shift[c4 + 2]);
        r.w = fmaxf(0.0f, v.w * s_scale[c4 + 3] + s_shift[c4 + 3]);
        ((float4*)out)[idx] = r;
    }
}

// ---------------- launcher ----------------
extern "C" void kernel_launch(void* const* d_in, const int* in_sizes, int n_in,
                              void* d_out, int out_size) {
    const float* x     = (const float*)d_in[0];
    const int*   ei    = (const int*)d_in[1];
    const float* W     = (const float*)d_in[2];
    // d_in[3] = b : mathematically absorbed by batchnorm, unused
    const float* gamma = (const float*)d_in[4];
    const float* beta  = (const float*)d_in[5];
    float* out = (float*)d_out;

    int n = in_sizes[0] / DD;
    int E = in_sizes[1] / 2;
    const int* src = ei;
    const int* dst = ei + E;
    float inv_n = 1.0f / (float)n;

    cudaFuncSetAttribute(gemm_tc_kernel,
                         cudaFuncAttributeMaxDynamicSharedMemorySize, SMEM_GEMM);

    // fork: CSR chain on side stream, W-split + GEMM0 on launch stream
    cudaStream_t s2;
    cudaEvent_t ev_fork, ev_join;
    cudaStreamCreateWithFlags(&s2, cudaStreamNonBlocking);
    cudaEventCreateWithFlags(&ev_fork, cudaEventDisableTiming);
    cudaEventCreateWithFlags(&ev_join, cudaEventDisableTiming);

    cudaEventRecord(ev_fork, 0);
    cudaStreamWaitEvent(s2, ev_fork, 0);

    // CSR chain (side stream)
    zero_cnt_kernel<<<(n + 255) / 256, 256, 0, s2>>>(n);
    hist_kernel<<<(E + 255) / 256, 256, 0, s2>>>(dst, E);
    alloc_dinv_kernel<<<(n + 255) / 256, 256, 0, s2>>>(n);
    edge_sort_kernel<<<(E + 255) / 256, 256, 0, s2>>>(src, dst, E);
    cudaEventRecord(ev_join, s2);

    // GEMM chain (launch stream)
    split_w_kernel<<<(LAYERS * DD * DD + 255) / 256, 256>>>(W);
    gemm_tc_kernel<<<(n + 127) / 128, 256, SMEM_GEMM>>>(
        x, 0, 0, gamma, beta, inv_n, n);

    // join before first gather
    cudaStreamWaitEvent(0, ev_join, 0);

    gather_stats_kernel<<<512, 256>>>(0, n);
    for (int l = 1; l < LAYERS; l++) {
        gemm_tc_kernel<<<(n + 127) / 128, 256, SMEM_GEMM>>>(
            x, 1, l, gamma, beta, inv_n, n);
        gather_stats_kernel<<<512, 256>>>(l, n);
    }
    norm_relu_kernel<<<512, 256>>>(out, gamma, beta, inv_n, n);
}